// round 8
// baseline (speedup 1.0000x reference)
#include <cuda_runtime.h>
#include <math.h>

#define B 64
#define S 512
#define H 768
#define K 64

// Scratch
__device__ float g_scores[3 * B * K];
__device__ float g_pooled[3 * B * H];

// ---------------------------------------------------------------------------
// K1: raw scores[j] = dot(G0, Gj), j < len only. grid (B, 3, 4), block 256.
// g0 staged in smem (warp-invariant) to keep regs low; av/bv MLP-12 in regs.
// Block (0,0,0) also initializes out[] with classifier biases.
// ---------------------------------------------------------------------------
__global__ void __launch_bounds__(256)
score_kernel(const float* __restrict__ seq,
             const int* __restrict__ idx0, const int* __restrict__ len0,
             const int* __restrict__ idx1, const int* __restrict__ len1,
             const int* __restrict__ idx2, const int* __restrict__ len2,
             const float* __restrict__ bc0,
             const float* __restrict__ bc1,
             const float* __restrict__ bc2,
             float* __restrict__ out) {
    int b  = blockIdx.x;
    int t  = blockIdx.y;
    int jt = blockIdx.z;           // 16 j's per block
    const int* idxp = (t == 0) ? idx0 : (t == 1) ? idx1 : idx2;
    const int* lenp = (t == 0) ? len0 : (t == 1) ? len1 : len2;

    __shared__ float4 g0s[192];    // row 0 (768 floats)
    __shared__ int sidx[16];
    __shared__ int si0;

    int tid  = threadIdx.x;
    int wid  = tid >> 5;
    int lane = tid & 31;

    // bias init (layout: rel 64x9 | nov 64x3 | dir 64x3)
    if (b == 0 && t == 0 && jt == 0) {
        for (int i = tid; i < 960; i += 256) {
            float v;
            if (i < 576)      v = bc0[i % 9];
            else if (i < 768) v = bc1[(i - 576) % 3];
            else              v = bc2[(i - 768) % 3];
            out[i] = v;
        }
    }

    int len = lenp[b];
    int j0  = jt * 16;
    if (j0 >= len) return;          // block-uniform early out (bias done above)

    if (tid < 16) sidx[tid] = idxp[b * K + j0 + tid];
    if (tid == 16) si0 = idxp[b * K];
    __syncthreads();

    const float* seqb = seq + (size_t)b * S * H;

    if (tid < 192) g0s[tid] = ((const float4*)(seqb + (size_t)si0 * H))[tid];
    __syncthreads();

    bool doa = (j0 + wid)     < len;
    bool dob = (j0 + wid + 8) < len;
    // masked rows alias row sidx[0] (valid memory, result discarded)
    const float4* ga = (const float4*)(seqb + (size_t)sidx[doa ? wid : 0] * H);
    const float4* gb = (const float4*)(seqb + (size_t)sidx[dob ? wid + 8 : 0] * H);

    if (!doa) return;  // warp-uniform; no further barriers below

    float4 av[6], bv[6];
    if (dob) {
        #pragma unroll
        for (int i = 0; i < 6; i++) { av[i] = ga[lane + 32 * i]; bv[i] = gb[lane + 32 * i]; }
    } else {
        #pragma unroll
        for (int i = 0; i < 6; i++) { av[i] = ga[lane + 32 * i]; bv[i] = make_float4(0,0,0,0); }
    }

    float sa = 0.f, sb = 0.f;
    #pragma unroll
    for (int i = 0; i < 6; i++) {
        float4 g0v = g0s[lane + 32 * i];
        sa += g0v.x * av[i].x + g0v.y * av[i].y
            + g0v.z * av[i].z + g0v.w * av[i].w;
        sb += g0v.x * bv[i].x + g0v.y * bv[i].y
            + g0v.z * bv[i].z + g0v.w * bv[i].w;
    }
    #pragma unroll
    for (int o = 16; o; o >>= 1) {
        sa += __shfl_xor_sync(0xffffffffu, sa, o);
        sb += __shfl_xor_sync(0xffffffffu, sb, o);
    }
    if (lane == 0) {
        float* dst = &g_scores[((size_t)t * B + b) * K + j0];
        dst[wid] = sa;
        if (dob) dst[wid + 8] = sb;
    }
}

// ---------------------------------------------------------------------------
// K2: softmax + weighted sum (j < len). grid (B, 3, 4 htiles of 192), block 192.
// ---------------------------------------------------------------------------
__global__ void pool_kernel(const float* __restrict__ seq,
                            const int* __restrict__ idx0, const int* __restrict__ len0,
                            const int* __restrict__ idx1, const int* __restrict__ len1,
                            const int* __restrict__ idx2, const int* __restrict__ len2) {
    int b  = blockIdx.x;
    int t  = blockIdx.y;
    int h0 = blockIdx.z * 192;
    const int* idxp = (t == 0) ? idx0 : (t == 1) ? idx1 : idx2;
    const int* lenp = (t == 0) ? len0 : (t == 1) ? len1 : len2;

    __shared__ float prob[K];
    __shared__ int   sidx[K];

    int tid  = threadIdx.x;
    int lane = tid & 31;
    int len  = lenp[b];

    if (tid < K) sidx[tid] = idxp[b * K + tid];

    if (tid < 32) {
        const float* sc = &g_scores[((size_t)t * B + b) * K];
        float sa = (lane      < len) ? sc[lane]      : -1e30f;
        float sb = (lane + 32 < len) ? sc[lane + 32] : -1e30f;
        float m = fmaxf(sa, sb);
        #pragma unroll
        for (int o = 16; o; o >>= 1) m = fmaxf(m, __shfl_xor_sync(0xffffffffu, m, o));
        float ea = (lane      < len) ? expf(sa - m) : 0.f;
        float eb = (lane + 32 < len) ? expf(sb - m) : 0.f;
        float sum = ea + eb;
        #pragma unroll
        for (int o = 16; o; o >>= 1) sum += __shfl_xor_sync(0xffffffffu, sum, o);
        float inv = (sum > 0.f) ? (1.0f / sum) : 0.f;
        prob[lane]      = ea * inv;
        prob[lane + 32] = eb * inv;
    }
    __syncthreads();

    const float* base = seq + (size_t)b * S * H + h0 + tid;
    float acc = 0.f;
    #pragma unroll 16
    for (int j = 0; j < len; j++) {
        acc += prob[j] * base[(size_t)sidx[j] * H];
    }
    if (len == 0) acc = base[0];
    g_pooled[((size_t)t * B + b) * H + h0 + tid] = acc;
}

// ---------------------------------------------------------------------------
// K3: h = tanh(P @ Wd^T + bd) tile + fused classifier.
// grid (12 rtiles of 64, 4 btiles of 16, 3), block 256 (proven R4 config)
// with register-prefetched (software-pipelined) tile staging.
// Thread GEMM tile: rows {2tx, 2tx+1} x batches {2ty, 2ty+1}.
// ---------------------------------------------------------------------------
__global__ void __launch_bounds__(256)
dense_kernel(const float* __restrict__ Wd0, const float* __restrict__ bd0,
             const float* __restrict__ Wd1, const float* __restrict__ bd1,
             const float* __restrict__ Wd2, const float* __restrict__ bd2,
             const float* __restrict__ Wc0,
             const float* __restrict__ Wc1,
             const float* __restrict__ Wc2,
             float* __restrict__ out) {
    int t = blockIdx.z;
    const float* Wd = (t == 0) ? Wd0 : (t == 1) ? Wd1 : Wd2;
    const float* bd = (t == 0) ? bd0 : (t == 1) ? bd1 : bd2;
    const float* Wc = (t == 0) ? Wc0 : (t == 1) ? Wc1 : Wc2;
    int nlab   = (t == 0) ? 9 : 3;
    int outoff = (t == 0) ? 0 : (t == 1) ? B * 9 : B * 9 + B * 3;

    int r0 = blockIdx.x * 64;
    int b0 = blockIdx.y * 16;

    __shared__ float Ws[32][66];   // Ws[kk][r]
    __shared__ float Ps[16][32];   // Ps[bb][kk]
    __shared__ float Hs[16][66];   // h tile, batch-major

    int tid = threadIdx.x;
    int tx = tid & 31;    // rows 2tx, 2tx+1
    int ty = tid >> 5;    // batches 2ty, 2ty+1

    float acc[2][2] = {{0.f, 0.f}, {0.f, 0.f}};   // [batch][row]

    const float* P = g_pooled + (size_t)t * B * H;

    // staging maps (per thread):
    //  W: 8 scalars, id = tid + 256i -> r = id>>5 (0..63), kk = id&31 (coalesced)
    //  P: 2 scalars, id = tid + 256i -> bb = id>>5 (0..15), kk = id&31
    float wreg[8];
    float preg[2];
    #pragma unroll
    for (int i = 0; i < 8; i++) {
        int id = tid + 256 * i;
        wreg[i] = Wd[(size_t)(r0 + (id >> 5)) * H + (id & 31)];
    }
    #pragma unroll
    for (int i = 0; i < 2; i++) {
        int id = tid + 256 * i;
        preg[i] = P[(size_t)(b0 + (id >> 5)) * H + (id & 31)];
    }

    for (int k0 = 0; k0 < H; k0 += 32) {
        // commit prefetched tile to smem
        #pragma unroll
        for (int i = 0; i < 8; i++) {
            int id = tid + 256 * i;
            Ws[id & 31][id >> 5] = wreg[i];
        }
        #pragma unroll
        for (int i = 0; i < 2; i++) {
            int id = tid + 256 * i;
            Ps[id >> 5][id & 31] = preg[i];
        }
        __syncthreads();

        // prefetch next tile (overlaps with compute below)
        if (k0 + 32 < H) {
            #pragma unroll
            for (int i = 0; i < 8; i++) {
                int id = tid + 256 * i;
                wreg[i] = Wd[(size_t)(r0 + (id >> 5)) * H + (k0 + 32) + (id & 31)];
            }
            #pragma unroll
            for (int i = 0; i < 2; i++) {
                int id = tid + 256 * i;
                preg[i] = P[(size_t)(b0 + (id >> 5)) * H + (k0 + 32) + (id & 31)];
            }
        }

        #pragma unroll
        for (int kk = 0; kk < 32; kk++) {
            float w0 = Ws[kk][2 * tx];
            float w1 = Ws[kk][2 * tx + 1];
            float p0 = Ps[2 * ty][kk];
            float p1 = Ps[2 * ty + 1][kk];
            acc[0][0] += p0 * w0;  acc[0][1] += p0 * w1;
            acc[1][0] += p1 * w0;  acc[1][1] += p1 * w1;
        }
        __syncthreads();
    }

    int r = 2 * tx;
    float bdr0 = bd[r0 + r];
    float bdr1 = bd[r0 + r + 1];
    #pragma unroll
    for (int bb = 0; bb < 2; bb++) {
        Hs[2 * ty + bb][r]     = tanhf(acc[bb][0] + bdr0);
        Hs[2 * ty + bb][r + 1] = tanhf(acc[bb][1] + bdr1);
    }
    __syncthreads();

    // Fused classifier: warp ty handles batches 2ty, 2ty+1.
    int lane = tx;
    #pragma unroll
    for (int bb = 0; bb < 2; bb++) {
        int bl = 2 * ty + bb;
        float h0v = Hs[bl][lane];
        float h1v = Hs[bl][lane + 32];
        for (int l = 0; l < nlab; l++) {
            const float* wr = Wc + (size_t)l * H + r0;
            float s = h0v * __ldg(wr + lane) + h1v * __ldg(wr + lane + 32);
            #pragma unroll
            for (int o = 16; o; o >>= 1) s += __shfl_xor_sync(0xffffffffu, s, o);
            if (lane == 0)
                atomicAdd(&out[outoff + (b0 + bl) * nlab + l], s);
        }
    }
}

// ---------------------------------------------------------------------------
extern "C" void kernel_launch(void* const* d_in, const int* in_sizes, int n_in,
                              void* d_out, int out_size) {
    const float* seq      = (const float*)d_in[0];
    const int*   rel_idx  = (const int*)d_in[1];
    const int*   rel_len  = (const int*)d_in[2];
    const int*   nov_idx  = (const int*)d_in[3];
    const int*   nov_len  = (const int*)d_in[4];
    const int*   dir_idx  = (const int*)d_in[5];
    const int*   dir_len  = (const int*)d_in[6];
    const float* rel_dW   = (const float*)d_in[7];
    const float* rel_db   = (const float*)d_in[8];
    const float* rel_cW   = (const float*)d_in[9];
    const float* rel_cb   = (const float*)d_in[10];
    const float* nov_dW   = (const float*)d_in[11];
    const float* nov_db   = (const float*)d_in[12];
    const float* nov_cW   = (const float*)d_in[13];
    const float* nov_cb   = (const float*)d_in[14];
    const float* dir_dW   = (const float*)d_in[15];
    const float* dir_db   = (const float*)d_in[16];
    const float* dir_cW   = (const float*)d_in[17];
    const float* dir_cb   = (const float*)d_in[18];
    float* out = (float*)d_out;

    score_kernel<<<dim3(B, 3, 4), 256>>>(seq, rel_idx, rel_len, nov_idx, nov_len,
                                         dir_idx, dir_len,
                                         rel_cb, nov_cb, dir_cb, out);
    pool_kernel<<<dim3(B, 3, 4), 192>>>(seq, rel_idx, rel_len, nov_idx, nov_len,
                                        dir_idx, dir_len);
    dense_kernel<<<dim3(12, 4, 3), 256>>>(rel_dW, rel_db, nov_dW, nov_db,
                                          dir_dW, dir_db,
                                          rel_cW, nov_cW, dir_cW, out);
}

// round 9
// speedup vs baseline: 1.1020x; 1.1020x over previous
#include <cuda_runtime.h>
#include <math.h>

#define B 64
#define S 512
#define H 768
#define K 64

// Scratch
__device__ float g_scores[3 * B * K];
__device__ float g_pooled[3 * B * H];

// ---------------------------------------------------------------------------
// K1: raw scores[j] = dot(G0, Gj), j < len only. grid (B, 3, 4), block 256.
// g0 staged in smem (warp-invariant); av/bv MLP-12 in regs.
// Block (0,0,0) also initializes out[] with classifier biases.
// ---------------------------------------------------------------------------
__global__ void __launch_bounds__(256)
score_kernel(const float* __restrict__ seq,
             const int* __restrict__ idx0, const int* __restrict__ len0,
             const int* __restrict__ idx1, const int* __restrict__ len1,
             const int* __restrict__ idx2, const int* __restrict__ len2,
             const float* __restrict__ bc0,
             const float* __restrict__ bc1,
             const float* __restrict__ bc2,
             float* __restrict__ out) {
    int b  = blockIdx.x;
    int t  = blockIdx.y;
    int jt = blockIdx.z;           // 16 j's per block
    const int* idxp = (t == 0) ? idx0 : (t == 1) ? idx1 : idx2;
    const int* lenp = (t == 0) ? len0 : (t == 1) ? len1 : len2;

    __shared__ float4 g0s[192];    // row 0 (768 floats)
    __shared__ int sidx[16];
    __shared__ int si0;

    int tid  = threadIdx.x;
    int wid  = tid >> 5;
    int lane = tid & 31;

    // bias init (layout: rel 64x9 | nov 64x3 | dir 64x3)
    if (b == 0 && t == 0 && jt == 0) {
        for (int i = tid; i < 960; i += 256) {
            float v;
            if (i < 576)      v = bc0[i % 9];
            else if (i < 768) v = bc1[(i - 576) % 3];
            else              v = bc2[(i - 768) % 3];
            out[i] = v;
        }
    }

    int len = lenp[b];
    int j0  = jt * 16;
    if (j0 >= len) return;          // block-uniform early out (bias done above)

    if (tid < 16) sidx[tid] = idxp[b * K + j0 + tid];
    if (tid == 16) si0 = idxp[b * K];
    __syncthreads();

    const float* seqb = seq + (size_t)b * S * H;

    if (tid < 192) g0s[tid] = ((const float4*)(seqb + (size_t)si0 * H))[tid];
    __syncthreads();

    bool doa = (j0 + wid)     < len;
    bool dob = (j0 + wid + 8) < len;
    // masked rows alias row sidx[0] (valid memory, result discarded)
    const float4* ga = (const float4*)(seqb + (size_t)sidx[doa ? wid : 0] * H);
    const float4* gb = (const float4*)(seqb + (size_t)sidx[dob ? wid + 8 : 0] * H);

    if (!doa) return;  // warp-uniform; no further barriers below

    float4 av[6], bv[6];
    if (dob) {
        #pragma unroll
        for (int i = 0; i < 6; i++) { av[i] = ga[lane + 32 * i]; bv[i] = gb[lane + 32 * i]; }
    } else {
        #pragma unroll
        for (int i = 0; i < 6; i++) { av[i] = ga[lane + 32 * i]; bv[i] = make_float4(0,0,0,0); }
    }

    float sa = 0.f, sb = 0.f;
    #pragma unroll
    for (int i = 0; i < 6; i++) {
        float4 g0v = g0s[lane + 32 * i];
        sa += g0v.x * av[i].x + g0v.y * av[i].y
            + g0v.z * av[i].z + g0v.w * av[i].w;
        sb += g0v.x * bv[i].x + g0v.y * bv[i].y
            + g0v.z * bv[i].z + g0v.w * bv[i].w;
    }
    #pragma unroll
    for (int o = 16; o; o >>= 1) {
        sa += __shfl_xor_sync(0xffffffffu, sa, o);
        sb += __shfl_xor_sync(0xffffffffu, sb, o);
    }
    if (lane == 0) {
        float* dst = &g_scores[((size_t)t * B + b) * K + j0];
        dst[wid] = sa;
        if (dob) dst[wid + 8] = sb;
    }
}

// ---------------------------------------------------------------------------
// K2: softmax + weighted sum (j < len). grid (B, 3, 4 htiles of 192), block 192.
// ---------------------------------------------------------------------------
__global__ void pool_kernel(const float* __restrict__ seq,
                            const int* __restrict__ idx0, const int* __restrict__ len0,
                            const int* __restrict__ idx1, const int* __restrict__ len1,
                            const int* __restrict__ idx2, const int* __restrict__ len2) {
    int b  = blockIdx.x;
    int t  = blockIdx.y;
    int h0 = blockIdx.z * 192;
    const int* idxp = (t == 0) ? idx0 : (t == 1) ? idx1 : idx2;
    const int* lenp = (t == 0) ? len0 : (t == 1) ? len1 : len2;

    __shared__ float prob[K];
    __shared__ int   sidx[K];

    int tid  = threadIdx.x;
    int lane = tid & 31;
    int len  = lenp[b];

    if (tid < K) sidx[tid] = idxp[b * K + tid];

    if (tid < 32) {
        const float* sc = &g_scores[((size_t)t * B + b) * K];
        float sa = (lane      < len) ? sc[lane]      : -1e30f;
        float sb = (lane + 32 < len) ? sc[lane + 32] : -1e30f;
        float m = fmaxf(sa, sb);
        #pragma unroll
        for (int o = 16; o; o >>= 1) m = fmaxf(m, __shfl_xor_sync(0xffffffffu, m, o));
        float ea = (lane      < len) ? expf(sa - m) : 0.f;
        float eb = (lane + 32 < len) ? expf(sb - m) : 0.f;
        float sum = ea + eb;
        #pragma unroll
        for (int o = 16; o; o >>= 1) sum += __shfl_xor_sync(0xffffffffu, sum, o);
        float inv = (sum > 0.f) ? (1.0f / sum) : 0.f;
        prob[lane]      = ea * inv;
        prob[lane + 32] = eb * inv;
    }
    __syncthreads();

    const float* base = seq + (size_t)b * S * H + h0 + tid;
    float acc = 0.f;
    #pragma unroll 16
    for (int j = 0; j < len; j++) {
        acc += prob[j] * base[(size_t)sidx[j] * H];
    }
    if (len == 0) acc = base[0];
    g_pooled[((size_t)t * B + b) * H + h0 + tid] = acc;
}

// ---------------------------------------------------------------------------
// K3: h = tanh(P @ Wd^T + bd) tile + fused classifier.
// grid (12 rtiles of 64, 4 btiles of 16, 3), block 256. R4 staging (no
// prefetch); inner loop uses LDS.64 for both W (row pair) and P (batch pair).
// Thread GEMM tile: rows {2tx, 2tx+1} x batches {2ty, 2ty+1}.
// ---------------------------------------------------------------------------
__global__ void __launch_bounds__(256)
dense_kernel(const float* __restrict__ Wd0, const float* __restrict__ bd0,
             const float* __restrict__ Wd1, const float* __restrict__ bd1,
             const float* __restrict__ Wd2, const float* __restrict__ bd2,
             const float* __restrict__ Wc0,
             const float* __restrict__ Wc1,
             const float* __restrict__ Wc2,
             float* __restrict__ out) {
    int t = blockIdx.z;
    const float* Wd = (t == 0) ? Wd0 : (t == 1) ? Wd1 : Wd2;
    const float* bd = (t == 0) ? bd0 : (t == 1) ? bd1 : bd2;
    const float* Wc = (t == 0) ? Wc0 : (t == 1) ? Wc1 : Wc2;
    int nlab   = (t == 0) ? 9 : 3;
    int outoff = (t == 0) ? 0 : (t == 1) ? B * 9 : B * 9 + B * 3;

    int r0 = blockIdx.x * 64;
    int b0 = blockIdx.y * 16;

    __shared__ float Ws[32][66];   // Ws[kk][r]; row base 264B (8B aligned)
    __shared__ float Pt[32][18];   // Pt[kk][bb]; row base 72B (8B aligned)
    __shared__ float Hs[16][66];   // h tile, batch-major

    int tid = threadIdx.x;
    int tx = tid & 31;    // rows 2tx, 2tx+1
    int ty = tid >> 5;    // batches 2ty, 2ty+1

    float acc[2][2] = {{0.f, 0.f}, {0.f, 0.f}};   // [batch][row]

    const float* P = g_pooled + (size_t)t * B * H;

    for (int k0 = 0; k0 < H; k0 += 32) {
        #pragma unroll
        for (int i = 0; i < 8; i++) {
            int id = tid + 256 * i;
            int r  = id >> 5;
            int kk = id & 31;
            Ws[kk][r] = Wd[(size_t)(r0 + r) * H + (k0 + kk)];
        }
        #pragma unroll
        for (int i = 0; i < 2; i++) {
            int id = tid + 256 * i;
            int bb = id >> 5;
            int kk = id & 31;
            Pt[kk][bb] = P[(size_t)(b0 + bb) * H + (k0 + kk)];
        }
        __syncthreads();

        #pragma unroll
        for (int kk = 0; kk < 32; kk++) {
            float2 wv = *(const float2*)&Ws[kk][2 * tx];       // LDS.64
            float2 pv = *(const float2*)&Pt[kk][2 * ty];       // LDS.64 bcast
            acc[0][0] += pv.x * wv.x;  acc[0][1] += pv.x * wv.y;
            acc[1][0] += pv.y * wv.x;  acc[1][1] += pv.y * wv.y;
        }
        __syncthreads();
    }

    int r = 2 * tx;
    float bdr0 = bd[r0 + r];
    float bdr1 = bd[r0 + r + 1];
    #pragma unroll
    for (int bb = 0; bb < 2; bb++) {
        Hs[2 * ty + bb][r]     = tanhf(acc[bb][0] + bdr0);
        Hs[2 * ty + bb][r + 1] = tanhf(acc[bb][1] + bdr1);
    }
    __syncthreads();

    // Fused classifier: warp ty handles batches 2ty, 2ty+1.
    int lane = tx;
    #pragma unroll
    for (int bb = 0; bb < 2; bb++) {
        int bl = 2 * ty + bb;
        float h0v = Hs[bl][lane];
        float h1v = Hs[bl][lane + 32];
        for (int l = 0; l < nlab; l++) {
            const float* wr = Wc + (size_t)l * H + r0;
            float s = h0v * __ldg(wr + lane) + h1v * __ldg(wr + lane + 32);
            #pragma unroll
            for (int o = 16; o; o >>= 1) s += __shfl_xor_sync(0xffffffffu, s, o);
            if (lane == 0)
                atomicAdd(&out[outoff + (b0 + bl) * nlab + l], s);
        }
    }
}

// ---------------------------------------------------------------------------
extern "C" void kernel_launch(void* const* d_in, const int* in_sizes, int n_in,
                              void* d_out, int out_size) {
    const float* seq      = (const float*)d_in[0];
    const int*   rel_idx  = (const int*)d_in[1];
    const int*   rel_len  = (const int*)d_in[2];
    const int*   nov_idx  = (const int*)d_in[3];
    const int*   nov_len  = (const int*)d_in[4];
    const int*   dir_idx  = (const int*)d_in[5];
    const int*   dir_len  = (const int*)d_in[6];
    const float* rel_dW   = (const float*)d_in[7];
    const float* rel_db   = (const float*)d_in[8];
    const float* rel_cW   = (const float*)d_in[9];
    const float* rel_cb   = (const float*)d_in[10];
    const float* nov_dW   = (const float*)d_in[11];
    const float* nov_db   = (const float*)d_in[12];
    const float* nov_cW   = (const float*)d_in[13];
    const float* nov_cb   = (const float*)d_in[14];
    const float* dir_dW   = (const float*)d_in[15];
    const float* dir_db   = (const float*)d_in[16];
    const float* dir_cW   = (const float*)d_in[17];
    const float* dir_cb   = (const float*)d_in[18];
    float* out = (float*)d_out;

    score_kernel<<<dim3(B, 3, 4), 256>>>(seq, rel_idx, rel_len, nov_idx, nov_len,
                                         dir_idx, dir_len,
                                         rel_cb, nov_cb, dir_cb, out);
    pool_kernel<<<dim3(B, 3, 4), 192>>>(seq, rel_idx, rel_len, nov_idx, nov_len,
                                        dir_idx, dir_len);
    dense_kernel<<<dim3(12, 4, 3), 256>>>(rel_dW, rel_db, nov_dW, nov_db,
                                          dir_dW, dir_db,
                                          rel_cW, nov_cW, dir_cW, out);
}